// round 17
// baseline (speedup 1.0000x reference)
#include <cuda_runtime.h>
#include <cuda_fp16.h>
#include <cstdint>
#include <math.h>

#define NB 16384
#define NS 2048
#define ND 512
#define NM (NB + NS)   // 18432 rows: [x ; samples]

// ---------------------------------------------------------------------------
// Scratch (__device__ globals — allocation-free contract)
// ---------------------------------------------------------------------------
__device__ __align__(16) __half g_cath [NM * ND];            // [x ; samples] fp16
__device__ __align__(16) __half g_t1h  [NM * ND];            // dml hidden fp16
__device__ __align__(16) __half g_dmlh [NM * ND];            // [x_dml ; sam_new] fp16
__device__ __align__(16) __half g_W1h  [ND * ND];
__device__ __align__(16) __half g_W2h  [ND * ND];
__device__ __align__(16) __half g_Wn1h [NS * NS];
__device__ __align__(16) __half g_Wn2h [NS * NS];
__device__ __align__(16) __half g_Kh   [(long long)NB * NS]; // K fp16 (scaled, direct)
__device__ __align__(16) __half g_Hh   [(long long)NB * NS]; // h fp16 (scaled)
__device__ __align__(16) float  g_nrm  [NM];
__device__ unsigned g_minD2est;    // bit-pattern of SAMPLED min d2 (>= 0)

// ---------------------------------------------------------------------------
// Helpers
// ---------------------------------------------------------------------------
__device__ __forceinline__ uint32_t smem_u32(const void* p) {
    uint32_t a;
    asm("{ .reg .u64 t; cvta.to.shared.u64 t, %1; cvt.u32.u64 %0, t; }" : "=r"(a) : "l"(p));
    return a;
}
__device__ __forceinline__ float mish_f(float z) {
    float e  = __expf(z);
    float w  = 1.0f + e;
    float w2 = w * w;
    float r  = __fdividef(w2 - 1.0f, w2 + 1.0f);
    return (z > 30.0f) ? z : z * r;
}
__device__ __forceinline__ void cp_async16(uint32_t saddr, const void* gaddr) {
    asm volatile("cp.async.cg.shared.global [%0], [%1], 16;" :: "r"(saddr), "l"(gaddr) : "memory");
}
__device__ __forceinline__ void cp_commit() {
    asm volatile("cp.async.commit_group;" ::: "memory");
}
__device__ __forceinline__ void ldsm4(uint32_t* d, uint32_t addr) {
    asm volatile("ldmatrix.sync.aligned.m8n8.x4.shared.b16 {%0,%1,%2,%3}, [%4];"
                 : "=r"(d[0]), "=r"(d[1]), "=r"(d[2]), "=r"(d[3]) : "r"(addr));
}
__device__ __forceinline__ void mma_f16(float* c, const uint32_t* a, uint32_t b0, uint32_t b1) {
    asm volatile("mma.sync.aligned.m16n8k16.row.col.f32.f16.f16.f32 "
                 "{%0,%1,%2,%3}, {%4,%5,%6,%7}, {%8,%9}, {%0,%1,%2,%3};"
                 : "+f"(c[0]), "+f"(c[1]), "+f"(c[2]), "+f"(c[3])
                 : "r"(a[0]), "r"(a[1]), "r"(a[2]), "r"(a[3]), "r"(b0), "r"(b1));
}
// E' = floor(-dist_est * log2 e). dist_est >= dmin  =>  E' <= E_true.
__device__ __forceinline__ int est_E() {
    float dm = sqrtf(__uint_as_float(g_minD2est));
    return (int)floorf(-dm * 1.44269504f);
}

enum { EPI_BIAS = 0, EPI_BIAS_MISH = 1, EPI_KEXP = 2, EPI_MISHS = 3, EPI_OUTS = 4 };

// ---------------------------------------------------------------------------
// fp16 mma.sync GEMM (measured-best shape: CTA 128x128, 8 warps 64x32, BK=64,
// 3-stage cp.async, 2 CTAs/SM).
//  EPI_KEXP : K = exp2((7-E') - dist*log2e) stored fp16 DIRECTLY (no fp32
//             master, no convert pass). Clamped at 60000 as overflow guard.
//  EPI_MISHS: z scaled by 2^(E'-7); h stored * 2^(3-E') (bound |h|<64*maxK).
//  EPI_OUTS : result * 2^(E'-3), fp32 out.
//  NORM_OUT : dml2 accumulates row norms of the STORED fp16 values.
// ---------------------------------------------------------------------------
#define A_BY     16384
#define STAGE_BY 32768
#define DSMEM_BY (3 * STAGE_BY)

template <int EPI, bool HALF_OUT, bool NORM_OUT>
__global__ void __launch_bounds__(256, 2)
gemm_h(const __half* __restrict__ A, const __half* __restrict__ B,
       void* __restrict__ Cv, int M, int N, int K,
       const float* __restrict__ e1, const float* __restrict__ e2,
       float* __restrict__ nrm_out)
{
    extern __shared__ float smem[];
    const uint32_t sbase = smem_u32(smem);

    const int tid  = threadIdx.x;
    const int wid  = tid >> 5;
    const int lane = tid & 31;
    const int wm   = wid & 1;
    const int wn   = wid >> 1;
    const int nk   = K >> 6;         // BK = 64 halves

    const uint32_t rowA0 = blockIdx.y * 128;
    const uint32_t rowB0 = blockIdx.x * 128;

    uint32_t sOff[4], gAo[4], gBo[4];
#pragma unroll
    for (int i = 0; i < 4; i++) {
        int c = tid + i * 256, row = c >> 3, ch = c & 7;
        sOff[i] = (uint32_t)((row * 8 + (ch ^ (row & 7))) * 16);
        gAo[i]  = (rowA0 + row) * (uint32_t)K + ch * 8;
        gBo[i]  = (rowB0 + row) * (uint32_t)K + ch * 8;
    }

    auto issue = [&](int fi) {
        const int s = fi % 3;
        const uint32_t k0 = (uint32_t)fi * 64;
        const uint32_t sA = sbase + s * STAGE_BY;
        const uint32_t sB = sA + A_BY;
#pragma unroll
        for (int i = 0; i < 4; i++) cp_async16(sA + sOff[i], A + gAo[i] + k0);
#pragma unroll
        for (int i = 0; i < 4; i++) cp_async16(sB + sOff[i], B + gBo[i] + k0);
        cp_commit();
    };

    const int r8    = lane & 7;
    const int matId = lane >> 3;
    const int mrow  = ((matId & 1) << 3) + r8;
    const int mhi   = matId >> 1;
    uint32_t csw[4], aRow[4], bRow[2];
#pragma unroll
    for (int ks = 0; ks < 4; ks++) csw[ks] = (uint32_t)(((2 * ks + mhi) ^ r8) << 4);
#pragma unroll
    for (int t = 0; t < 4; t++) aRow[t] = (uint32_t)((wm * 64 + t * 16 + mrow) * 128);
#pragma unroll
    for (int t = 0; t < 2; t++) bRow[t] = (uint32_t)((wn * 32 + t * 16 + mrow) * 128) + A_BY;

    float acc[4][4][4];
#pragma unroll
    for (int mt = 0; mt < 4; mt++)
#pragma unroll
        for (int nt = 0; nt < 4; nt++)
#pragma unroll
            for (int q = 0; q < 4; q++) acc[mt][nt][q] = 0.0f;

    issue(0);
    issue(1);

#pragma unroll 1
    for (int fi = 0; fi < nk; ++fi) {
        if (fi + 1 < nk) asm volatile("cp.async.wait_group 1;" ::: "memory");
        else             asm volatile("cp.async.wait_group 0;" ::: "memory");
        __syncthreads();
        if (fi + 2 < nk) issue(fi + 2);

        const uint32_t st = sbase + (fi % 3) * STAGE_BY;
#pragma unroll
        for (int ks = 0; ks < 4; ks++) {
            uint32_t a[4][4], bb[2][4];
#pragma unroll
            for (int mt = 0; mt < 4; mt++) ldsm4(a[mt],  st + aRow[mt] + csw[ks]);
#pragma unroll
            for (int np = 0; np < 2; np++) ldsm4(bb[np], st + bRow[np] + csw[ks]);
#pragma unroll
            for (int mt = 0; mt < 4; mt++)
#pragma unroll
                for (int nt = 0; nt < 4; nt++)
                    mma_f16(acc[mt][nt], a[mt], bb[nt >> 1][nt & 1], bb[nt >> 1][2 + (nt & 1)]);
        }
    }

    // ---- epilogue: scales derived from the pre-estimated min d2 ----
    float invs = 1.0f, osc = 1.0f, s13 = 0.0f;
    if (EPI == EPI_KEXP || EPI == EPI_MISHS || EPI == EPI_OUTS) {
        const int Ep = est_E();
        if (EPI == EPI_KEXP)  s13  = (float)(7 - Ep);
        if (EPI == EPI_MISHS) { invs = exp2f((float)(Ep - 7)); osc = exp2f((float)(3 - Ep)); }
        if (EPI == EPI_OUTS)  invs = exp2f((float)(Ep - 3));
    }
    const int gid = lane >> 2, tig = lane & 3;
    float*  Cf = (float*)Cv;
    __half* Ch = (__half*)Cv;
#pragma unroll
    for (int mt = 0; mt < 4; mt++) {
        const int row = blockIdx.y * 128 + wm * 64 + mt * 16 + gid;
        float nr0 = 0.0f, nr8 = 0.0f;
        if (EPI == EPI_KEXP) { nr0 = __ldg(e1 + row); nr8 = __ldg(e1 + row + 8); }
        float ns0 = 0.0f, ns8 = 0.0f;
#pragma unroll
        for (int nt = 0; nt < 4; nt++) {
            const int col = blockIdx.x * 128 + wn * 32 + nt * 8 + tig * 2;
            float ec0 = 0.0f, ec1 = 0.0f;
            if (EPI == EPI_BIAS || EPI == EPI_BIAS_MISH || EPI == EPI_KEXP) {
                const float* ee = (EPI == EPI_KEXP) ? e2 : e1;
                ec0 = __ldg(ee + col); ec1 = __ldg(ee + col + 1);
            }
            float v[4] = {acc[mt][nt][0], acc[mt][nt][1], acc[mt][nt][2], acc[mt][nt][3]};
#pragma unroll
            for (int q = 0; q < 4; q++) {
                float x = v[q] * invs;
                const float ec = (q & 1) ? ec1 : ec0;
                const float nr = (q < 2) ? nr0 : nr8;
                if (EPI == EPI_BIAS)           x = x + ec;
                else if (EPI == EPI_BIAS_MISH) x = mish_f(x + ec);
                else if (EPI == EPI_MISHS)     x = mish_f(x);
                else if (EPI == EPI_KEXP) {
                    float d2 = fmaxf(nr + ec - 2.0f * x, 0.0f);
                    float d;
                    asm("sqrt.approx.f32 %0, %1;" : "=f"(d) : "f"(d2));
                    x = fminf(exp2f(fmaf(-d, 1.44269504f, s13)), 60000.0f);
                }
                v[q] = x * osc;
            }
            if (HALF_OUT) {
                __half2 ha = __floats2half2_rn(v[0], v[1]);
                __half2 hb = __floats2half2_rn(v[2], v[3]);
                *(__half2*)(Ch + (size_t)row * N + col)       = ha;
                *(__half2*)(Ch + (size_t)(row + 8) * N + col) = hb;
                if (NORM_OUT) {
                    float2 fa = __half22float2(ha), fb = __half22float2(hb);
                    ns0 += fa.x * fa.x + fa.y * fa.y;
                    ns8 += fb.x * fb.x + fb.y * fb.y;
                }
            } else {
                *(float2*)(Cf + (size_t)row * N + col)       = make_float2(v[0], v[1]);
                *(float2*)(Cf + (size_t)(row + 8) * N + col) = make_float2(v[2], v[3]);
            }
        }
        if (NORM_OUT) {
            ns0 += __shfl_down_sync(0xffffffffu, ns0, 2);
            ns0 += __shfl_down_sync(0xffffffffu, ns0, 1);
            ns8 += __shfl_down_sync(0xffffffffu, ns8, 2);
            ns8 += __shfl_down_sync(0xffffffffu, ns8, 1);
            if (tig == 0) {
                atomicAdd(nrm_out + row,     ns0);
                atomicAdd(nrm_out + row + 8, ns8);
            }
        }
    }
}

// ---------------------------------------------------------------------------
// Fused input conversion (grid-stride): all six fp32 inputs -> fp16;
// zero nrm; init g_minD2est = +inf.
// ---------------------------------------------------------------------------
__device__ __forceinline__ void cvt_gs(const float4* in, uint2* out, int n4) {
    for (int i = blockIdx.x * 256 + threadIdx.x; i < n4; i += gridDim.x * 256) {
        float4 v = in[i];
        __half2 a = __floats2half2_rn(v.x, v.y);
        __half2 b = __floats2half2_rn(v.z, v.w);
        uint2 o;
        o.x = *(const unsigned*)&a;
        o.y = *(const unsigned*)&b;
        out[i] = o;
    }
}

__global__ void __launch_bounds__(256)
f2h_all(const float4* x, const float4* sm, const float4* w1, const float4* w2,
        const float4* wn1, const float4* wn2,
        uint2* cath, uint2* w1h, uint2* w2h, uint2* wn1h, uint2* wn2h,
        float4* nrm)
{
    switch (blockIdx.y) {
        case 0: cvt_gs(x,   cath,               NB * ND / 4); break;
        case 1: cvt_gs(sm,  cath + NB * ND / 4, NS * ND / 4); break;
        case 2: cvt_gs(w1,  w1h,                ND * ND / 4);
                for (int j = blockIdx.x * 256 + threadIdx.x; j < NM / 4; j += gridDim.x * 256)
                    nrm[j] = make_float4(0.f, 0.f, 0.f, 0.f);
                if (blockIdx.x == 0 && threadIdx.x == 0) g_minD2est = 0x7F800000u; // +inf
                break;
        case 3: cvt_gs(w2,  w2h,                ND * ND / 4); break;
        case 4: cvt_gs(wn1, wn1h,               NS * NS / 4); break;
        case 5: cvt_gs(wn2, wn2h,               NS * NS / 4); break;
    }
}

// ---------------------------------------------------------------------------
// dmin estimator: 128 strided x-rows x all 2048 samples (262144 pairs).
// Block b holds 16 samples in smem (padded stride vs bank conflicts) and
// streams the 128 sampled x-rows through smem. dist_est >= dmin always.
// ---------------------------------------------------------------------------
#define EST_ROWS 128
#define EST_STRIDE (NB / EST_ROWS)   // 128
#define SPAD 520                      // 1040B sample stride: 2-way conflicts max

__global__ void __launch_bounds__(256)
dmin_est(const __half* __restrict__ dml, const float* __restrict__ nrm)
{
    __shared__ __half ssam[16 * SPAD];
    __shared__ __half srow[16 * 512];
    __shared__ float  sns[16];
    __shared__ float  red[8];
    const int tid = threadIdx.x;
    const int j0  = blockIdx.x * 16;
    const __half* sam = dml + (size_t)NB * ND;

    // load 16 samples (uint4 = 8 halves; 64 chunks per sample)
    for (int k = tid; k < 16 * 64; k += 256) {
        int s = k >> 6, p = k & 63;
        *(uint4*)(ssam + s * SPAD + p * 8) =
            *(const uint4*)(sam + (size_t)(j0 + s) * ND + p * 8);
    }
    if (tid < 16) sns[tid] = nrm[NB + j0 + tid];

    float lmin = 3.4e38f;
    const int jl = tid & 15, rg = tid >> 4;
#pragma unroll 1
    for (int p = 0; p < EST_ROWS / 16; p++) {
        __syncthreads();
        for (int k = tid; k < 16 * 64; k += 256) {
            int rr = k >> 6, cc = k & 63;
            int row = (p * 16 + rr) * EST_STRIDE + 61;
            *(uint4*)(srow + rr * 512 + cc * 8) =
                *(const uint4*)(dml + (size_t)row * ND + cc * 8);
        }
        __syncthreads();
        const __half2* xr = (const __half2*)(srow + rg * 512);
        const __half2* sj = (const __half2*)(ssam + jl * SPAD);
        float a0 = 0.f, a1 = 0.f;
#pragma unroll 8
        for (int k = 0; k < 256; k++) {
            float2 a = __half22float2(xr[k]);
            float2 b = __half22float2(sj[k]);
            a0 = fmaf(a.x, b.x, a0);
            a1 = fmaf(a.y, b.y, a1);
        }
        const int row = (p * 16 + rg) * EST_STRIDE + 61;
        float d2 = nrm[row] + sns[jl] - 2.0f * (a0 + a1);
        lmin = fminf(lmin, fmaxf(d2, 0.0f));
    }
#pragma unroll
    for (int o = 16; o; o >>= 1) lmin = fminf(lmin, __shfl_xor_sync(0xffffffffu, lmin, o));
    if ((tid & 31) == 0) red[tid >> 5] = lmin;
    __syncthreads();
    if (tid == 0) {
        float m = red[0];
#pragma unroll
        for (int w = 1; w < 8; w++) m = fminf(m, red[w]);
        atomicMin(&g_minD2est, __float_as_uint(m));   // m >= 0: uint order == float order
    }
}

// ---------------------------------------------------------------------------
// Launch — 7 launches: f2h, dml1, dml2, estimator, d2->Kh, mish, out.
// ---------------------------------------------------------------------------
extern "C" void kernel_launch(void* const* d_in, const int* in_sizes, int n_in,
                              void* d_out, int out_size)
{
    const float* x   = (const float*)d_in[0];
    const float* sm  = (const float*)d_in[1];
    const float* W1  = (const float*)d_in[2];
    const float* b1  = (const float*)d_in[3];
    const float* W2  = (const float*)d_in[4];
    const float* b2  = (const float*)d_in[5];
    const float* Wn1 = (const float*)d_in[6];
    const float* Wn2 = (const float*)d_in[7];
    float* out = (float*)d_out;

    __half *cath, *t1h, *dmlh, *W1h, *W2h, *Wn1h, *Wn2h, *Kh, *Hh;
    float *nrm;
    cudaGetSymbolAddress((void**)&cath, g_cath);
    cudaGetSymbolAddress((void**)&t1h,  g_t1h);
    cudaGetSymbolAddress((void**)&dmlh, g_dmlh);
    cudaGetSymbolAddress((void**)&W1h,  g_W1h);
    cudaGetSymbolAddress((void**)&W2h,  g_W2h);
    cudaGetSymbolAddress((void**)&Wn1h, g_Wn1h);
    cudaGetSymbolAddress((void**)&Wn2h, g_Wn2h);
    cudaGetSymbolAddress((void**)&Kh,   g_Kh);
    cudaGetSymbolAddress((void**)&Hh,   g_Hh);
    cudaGetSymbolAddress((void**)&nrm,  g_nrm);

    #define SETSM(KER) cudaFuncSetAttribute(KER, cudaFuncAttributeMaxDynamicSharedMemorySize, DSMEM_BY)
    SETSM((gemm_h<EPI_BIAS_MISH, true,  false>));
    SETSM((gemm_h<EPI_BIAS,      true,  true >));
    SETSM((gemm_h<EPI_KEXP,      true,  false>));
    SETSM((gemm_h<EPI_MISHS,     true,  false>));
    SETSM((gemm_h<EPI_OUTS,      false, false>));
    #undef SETSM

    const dim3 blk(256);
    const dim3 gDml(ND / 128, NM / 128);
    const dim3 gBig(NS / 128, NB / 128);

    // idx 0: fused conversion of ALL inputs + zero nrm / init minD2est
    f2h_all<<<dim3(1024, 6), 256>>>(
        (const float4*)x, (const float4*)sm, (const float4*)W1, (const float4*)W2,
        (const float4*)Wn1, (const float4*)Wn2,
        (uint2*)cath, (uint2*)W1h, (uint2*)W2h, (uint2*)Wn1h, (uint2*)Wn2h,
        (float4*)nrm);

    // idx 1: dml layer 1 (fused x+samples)
    gemm_h<EPI_BIAS_MISH, true, false><<<gDml, blk, DSMEM_BY>>>(
        cath, W1h, t1h, NM, ND, ND, b1, nullptr, nullptr);

    // idx 2: dml layer 2 + fused row norms (of stored fp16 values)
    gemm_h<EPI_BIAS, true, true><<<gDml, blk, DSMEM_BY>>>(
        t1h, W2h, dmlh, NM, ND, ND, b2, nullptr, nrm);

    // idx 3: dmin estimator (262144 sampled pairs -> g_minD2est)
    dmin_est<<<NS / 16, 256>>>(dmlh, nrm);

    // idx 4: d2 GEMM -> scaled fp16 K DIRECTLY (no fp32 master, no convert)
    gemm_h<EPI_KEXP, true, false><<<gBig, blk, DSMEM_BY>>>(
        dmlh, dmlh + (size_t)NB * ND, Kh, NB, NS, ND, nrm, nrm + NB, nullptr);

    // idx 5: h' = mish((K' @ Wn1^T)*invK) * scH -> fp16
    gemm_h<EPI_MISHS, true, false><<<gBig, blk, DSMEM_BY>>>(
        Kh, Wn1h, Hh, NB, NS, NS, nullptr, nullptr, nullptr);

    // idx 6: out = (h' @ Wn2^T) * invH  (fp32)
    gemm_h<EPI_OUTS, false, false><<<gBig, blk, DSMEM_BY>>>(
        Hh, Wn2h, out, NB, NS, NS, nullptr, nullptr, nullptr);
}